// round 8
// baseline (speedup 1.0000x reference)
#include <cuda_runtime.h>

// Problem constants
#define BB   256      // batch
#define TT   512      // timesteps (only last one matters)
#define DIN  64
#define HIDN 64
#define NBAS 10
#define KDIM (DIN*NBAS)   // 640
#define NCLS 2

// Kernel config: 1 row per CTA, 2 CTAs per SM
#define NBLK  BB                // 256 blocks
#define NTHR  256
#define SPLIT 16                // split-k groups
#define KPER  (KDIM/SPLIT)      // 40 k-iters per thread
#define CHUNK 8                 // k-iters per pipelined chunk
#define NCH   (KPER/CHUNK)      // 5 chunks
#define REDW  68                // padded s_red row

__device__ __forceinline__ float fast_tanh(float y) {
    float e = __expf(2.0f * y);
    return 1.0f - __fdividef(2.0f, e + 1.0f);
}
__device__ __forceinline__ float fast_sigmoid(float y) {
    return __fdividef(1.0f, 1.0f + __expf(-y));
}

__global__ __launch_bounds__(NTHR, 2) void node_rnn_fused_kernel(
    const float* __restrict__ x,
    const float* __restrict__ c0, const float* __restrict__ w0, const float* __restrict__ C0,
    const float* __restrict__ c1, const float* __restrict__ w1, const float* __restrict__ C1,
    const float* __restrict__ c2, const float* __restrict__ w2, const float* __restrict__ C2,
    const float* __restrict__ Whead, const float* __restrict__ bhead,
    float* __restrict__ out)
{
    __shared__ float s_phi[KDIM];              // basis expansion of current stage input
    __shared__ float s_val[HIDN];              // final hidden (for head)
    __shared__ float s_red[SPLIT][REDW];       // split-k partials (padded)
    __shared__ float s_c[3][NBAS], s_iw[3][NBAS];
    __shared__ float s_x[DIN];
    __shared__ float s_W[HIDN * NCLS];
    __shared__ float s_b[NCLS];

    const int tid = threadIdx.x;
    const int row = blockIdx.x;

    // --- startup loads (independent, high MLP) ---
    if (tid < NBAS)        { s_c[0][tid]      = c0[tid];      s_iw[0][tid]      = __frcp_rn(w0[tid]); }
    else if (tid < 2*NBAS) { int k = tid-NBAS;   s_c[1][k] = c1[k]; s_iw[1][k] = __frcp_rn(w1[k]); }
    else if (tid < 3*NBAS) { int k = tid-2*NBAS; s_c[2][k] = c2[k]; s_iw[2][k] = __frcp_rn(w2[k]); }

    if (tid >= 32 && tid < 32 + HIDN * NCLS) s_W[tid - 32] = Whead[tid - 32];
    if (tid >= 160 && tid < 160 + NCLS)      s_b[tid - 160] = bhead[tid - 160];
    if (tid >= 192) {
        int i = tid - 192;   // 0..63
        s_x[i] = x[(size_t)row * (TT * DIN) + (size_t)(TT - 1) * DIN + i];
    }

    const int q   = tid & 15;        // output quad: columns 4q..4q+3
    const int g   = tid >> 4;        // split-k group 0..15
    const int kk0 = g * KPER;

    // reduce/phi assignment: 4 threads per hidden unit
    const int oo   = tid >> 2;       // hidden unit 0..63
    const int part = tid & 3;
    const int kbeg = (part < 2) ? part * 3 : 6 + (part - 2) * 2;  // {0,3,6,8}
    const int kcnt = (part < 2) ? 3 : 2;

    const float* Cs[3] = { C0, C1, C2 };

    // ---- pipelined coefficient buffers (persistent parity across stages) ----
    float4 buf[2][CHUNK];
    int cur = 0;
    #pragma unroll
    for (int j = 0; j < CHUNK; ++j)
        buf[0][j] = *reinterpret_cast<const float4*>(C0 + (size_t)(kk0 + j) * HIDN + 4 * q);

    __syncthreads();   // consts + x row ready

    // ---- stage-0 phi from x (all threads) ----
    #pragma unroll
    for (int it = tid; it < KDIM; it += NTHR) {
        int i = it / NBAS, k = it - i * NBAS;
        s_phi[it] = fast_tanh((s_x[i] - s_c[0][k]) * s_iw[0][k]);
    }
    __syncthreads();

    #pragma unroll
    for (int stage = 0; stage < 3; ++stage) {
        const float* __restrict__ C  = Cs[stage];
        const float* __restrict__ Cn = (stage < 2) ? Cs[stage + 1] : Cs[2];

        float a0 = 0.0f, a1 = 0.0f, a2 = 0.0f, a3 = 0.0f;

        #pragma unroll
        for (int ch = 0; ch < NCH; ++ch) {
            // prefetch next chunk (same stage) or next stage's chunk 0
            if (ch < NCH - 1) {
                #pragma unroll
                for (int j = 0; j < CHUNK; ++j)
                    buf[cur ^ 1][j] = *reinterpret_cast<const float4*>(
                        C + (size_t)(kk0 + (ch + 1) * CHUNK + j) * HIDN + 4 * q);
            } else if (stage < 2) {
                #pragma unroll
                for (int j = 0; j < CHUNK; ++j)
                    buf[cur ^ 1][j] = *reinterpret_cast<const float4*>(
                        Cn + (size_t)(kk0 + j) * HIDN + 4 * q);
            }
            // FMA over current chunk (phi via broadcast float4 LDS)
            float4 pA = *reinterpret_cast<const float4*>(&s_phi[kk0 + ch * CHUNK]);
            float4 pB = *reinterpret_cast<const float4*>(&s_phi[kk0 + ch * CHUNK + 4]);
            #pragma unroll
            for (int j = 0; j < CHUNK; ++j) {
                float p = (j == 0) ? pA.x : (j == 1) ? pA.y : (j == 2) ? pA.z : (j == 3) ? pA.w
                        : (j == 4) ? pB.x : (j == 5) ? pB.y : (j == 6) ? pB.z : pB.w;
                float4 c4 = buf[cur][j];
                a0 = fmaf(p, c4.x, a0);
                a1 = fmaf(p, c4.y, a1);
                a2 = fmaf(p, c4.z, a2);
                a3 = fmaf(p, c4.w, a3);
            }
            cur ^= 1;   // persistent parity: next stage reads the buffer just prefetched
        }

        // write split-k partials
        *reinterpret_cast<float4*>(&s_red[g][4 * q]) = make_float4(a0, a1, a2, a3);
        __syncthreads();

        // ---- reduce: 4 threads/output sum 4 partials each + butterfly ----
        float v = 0.0f;
        #pragma unroll
        for (int jj = 0; jj < 4; ++jj)
            v += s_red[part + 4 * jj][oo];
        v += __shfl_xor_sync(0xffffffffu, v, 1);
        v += __shfl_xor_sync(0xffffffffu, v, 2);   // all 4 threads now hold the full sum

        float h = (stage == 0) ? v : fast_sigmoid(v);

        if (stage < 2) {
            // fused: directly expand phi for the next stage (2-3 tanh per thread)
            const int st = stage + 1;
            #pragma unroll
            for (int t = 0; t < 3; ++t) {
                if (t < kcnt) {
                    int k = kbeg + t;
                    s_phi[oo * NBAS + k] = fast_tanh((h - s_c[st][k]) * s_iw[st][k]);
                }
            }
        } else {
            if (part == 0) s_val[oo] = h;
        }
        __syncthreads();
    }

    // ---- head: logits[c] = phi3 . W[:,c] + b[c] ----
    if (tid < NCLS) {
        float s = s_b[tid];
        #pragma unroll
        for (int o = 0; o < HIDN; ++o)
            s = fmaf(s_val[o], s_W[o * NCLS + tid], s);
        out[row * NCLS + tid] = s;
    }
}

extern "C" void kernel_launch(void* const* d_in, const int* in_sizes, int n_in,
                              void* d_out, int out_size) {
    (void)in_sizes; (void)n_in; (void)out_size;
    const float* x  = (const float*)d_in[0];
    const float* c0 = (const float*)d_in[1];
    const float* w0 = (const float*)d_in[2];
    const float* C0 = (const float*)d_in[3];
    const float* c1 = (const float*)d_in[4];
    const float* w1 = (const float*)d_in[5];
    const float* C1 = (const float*)d_in[6];
    const float* c2 = (const float*)d_in[7];
    const float* w2 = (const float*)d_in[8];
    const float* C2 = (const float*)d_in[9];
    const float* W  = (const float*)d_in[10];
    const float* b  = (const float*)d_in[11];
    float* out = (float*)d_out;

    node_rnn_fused_kernel<<<NBLK, NTHR>>>(x, c0, w0, C0, c1, w1, C1,
                                          c2, w2, C2, W, b, out);
}

// round 10
// speedup vs baseline: 1.1449x; 1.1449x over previous
#include <cuda_runtime.h>

// Problem constants
#define BB   256      // batch
#define TT   512      // timesteps (only last one matters)
#define DIN  64
#define HIDN 64
#define NBAS 10
#define KDIM (DIN*NBAS)   // 640
#define NCLS 2

// Kernel config (R6 base: 2 rows/CTA, 512 threads, 128 CTAs)
#define RPB   2
#define NBLK  (BB/RPB)          // 128 blocks
#define NTHR  512
#define SPLIT 32                // split-k groups
#define KPER  (KDIM/SPLIT)      // 20 k-iters per thread
#define REDW  68                // padded s_red row (conflict-free, 16B-aligned)

__device__ __forceinline__ float fast_tanh(float y) {
    float e = __expf(2.0f * y);
    return 1.0f - __fdividef(2.0f, e + 1.0f);
}
__device__ __forceinline__ float fast_sigmoid(float y) {
    return __fdividef(1.0f, 1.0f + __expf(-y));
}

__global__ __launch_bounds__(NTHR) void node_rnn_fused_kernel(
    const float* __restrict__ x,
    const float* __restrict__ c0, const float* __restrict__ w0, const float* __restrict__ C0,
    const float* __restrict__ c1, const float* __restrict__ w1, const float* __restrict__ C1,
    const float* __restrict__ c2, const float* __restrict__ w2, const float* __restrict__ C2,
    const float* __restrict__ Whead, const float* __restrict__ bhead,
    float* __restrict__ out)
{
    __shared__ float s_x  [RPB][DIN];                  // last-timestep input rows
    __shared__ float s_val[RPB][HIDN];                 // final hidden (head input)
    __shared__ float s_phi[RPB][KDIM];
    __shared__ float s_red[SPLIT][RPB][REDW];          // padded: conflict-free
    __shared__ float s_c[3][NBAS], s_iw[3][NBAS];
    __shared__ float s_W[HIDN * NCLS];
    __shared__ float s_b[NCLS];

    const int tid = threadIdx.x;
    const int r0  = blockIdx.x * RPB;

    // --- startup loads (independent, high MLP) ---
    if (tid < NBAS)        { s_c[0][tid]      = c0[tid];      s_iw[0][tid]      = __frcp_rn(w0[tid]); }
    else if (tid < 2*NBAS) { int k = tid-NBAS;   s_c[1][k] = c1[k]; s_iw[1][k] = __frcp_rn(w1[k]); }
    else if (tid < 3*NBAS) { int k = tid-2*NBAS; s_c[2][k] = c2[k]; s_iw[2][k] = __frcp_rn(w2[k]); }

    if (tid >= 128 && tid < 128 + HIDN * NCLS) s_W[tid - 128] = Whead[tid - 128];
    if (tid >= 384 && tid < 384 + NCLS)        s_b[tid - 384] = bhead[tid - 384];

    if (tid >= 256 && tid < 256 + RPB * DIN) {
        int t = tid - 256;
        int r = t >> 6, i = t & 63;
        s_x[r][i] = x[(size_t)(r0 + r) * (TT * DIN) + (size_t)(TT - 1) * DIN + i];
    }

    // GEMM mapping
    const int q   = tid & 15;        // output quad: columns 4q..4q+3
    const int g   = tid >> 4;        // split-k group 0..31
    const int kk0 = g * KPER;

    // warp-local reduce mapping: warp w reduces (r,u) pairs for units 4w..4w+3
    const int wid  = tid >> 5;
    const int lane = tid & 31;
    const int part = lane & 3;
    const int idx  = lane >> 2;      // 0..7
    const int rr   = idx >> 2;       // row 0..1
    const int uu   = (wid << 2) + (idx & 3);   // hidden unit 0..63
    const int kbeg = (part < 2) ? part * 3 : 6 + (part - 2) * 2;  // {0,3,6,8}
    const int kcnt = (part < 2) ? 3 : 2;

    const float* Cs[3] = { C0, C1, C2 };

    // ---- stage-0 coefficient loads (front-batched, whole stage) ----
    float4 cv[KPER];
    #pragma unroll
    for (int j = 0; j < KPER; ++j)
        cv[j] = *reinterpret_cast<const float4*>(C0 + (size_t)(kk0 + j) * HIDN + 4 * q);

    __syncthreads();   // consts + x rows ready

    // ---- stage-0 phi from x, spread across ALL threads ----
    #pragma unroll
    for (int it = tid; it < RPB * KDIM; it += NTHR) {
        int r = it / KDIM, rem = it - r * KDIM;
        int i = rem / NBAS, k = rem - i * NBAS;
        s_phi[r][rem] = fast_tanh((s_x[r][i] - s_c[0][k]) * s_iw[0][k]);
    }
    __syncthreads();

    #pragma unroll 1
    for (int stage = 0; stage < 3; ++stage) {
        // ---- split-k GEMM: registers (coeffs) x smem (phi, float4) ----
        float acc[RPB][4];
        #pragma unroll
        for (int r = 0; r < RPB; ++r)
            acc[r][0] = acc[r][1] = acc[r][2] = acc[r][3] = 0.0f;

        #pragma unroll
        for (int jj = 0; jj < KPER / 4; ++jj) {
            float4 p0 = *reinterpret_cast<const float4*>(&s_phi[0][kk0 + 4 * jj]);
            float4 p1 = *reinterpret_cast<const float4*>(&s_phi[1][kk0 + 4 * jj]);
            #pragma unroll
            for (int e = 0; e < 4; ++e) {
                float4 c4 = cv[4 * jj + e];
                float pa = (e == 0) ? p0.x : (e == 1) ? p0.y : (e == 2) ? p0.z : p0.w;
                float pb = (e == 0) ? p1.x : (e == 1) ? p1.y : (e == 2) ? p1.z : p1.w;
                acc[0][0] = fmaf(pa, c4.x, acc[0][0]);
                acc[0][1] = fmaf(pa, c4.y, acc[0][1]);
                acc[0][2] = fmaf(pa, c4.z, acc[0][2]);
                acc[0][3] = fmaf(pa, c4.w, acc[0][3]);
                acc[1][0] = fmaf(pb, c4.x, acc[1][0]);
                acc[1][1] = fmaf(pb, c4.y, acc[1][1]);
                acc[1][2] = fmaf(pb, c4.z, acc[1][2]);
                acc[1][3] = fmaf(pb, c4.w, acc[1][3]);
            }
        }

        // ---- prefetch NEXT stage's coefficients (cv regs now dead) ----
        if (stage < 2) {
            const float* __restrict__ Cn = Cs[stage + 1];
            #pragma unroll
            for (int j = 0; j < KPER; ++j)
                cv[j] = *reinterpret_cast<const float4*>(Cn + (size_t)(kk0 + j) * HIDN + 4 * q);
        }

        // ---- write partials ----
        #pragma unroll
        for (int r = 0; r < RPB; ++r)
            *reinterpret_cast<float4*>(&s_red[g][r][4 * q]) =
                make_float4(acc[r][0], acc[r][1], acc[r][2], acc[r][3]);
        __syncthreads();

        // ---- fused: warp-local reduce + activation + next-stage phi ----
        {
            float v = 0.0f;
            #pragma unroll
            for (int jj = 0; jj < 8; ++jj)
                v += s_red[part + 4 * jj][rr][uu];
            v += __shfl_xor_sync(0xffffffffu, v, 1);
            v += __shfl_xor_sync(0xffffffffu, v, 2);   // all 4 group threads hold the sum

            float h = (stage == 0) ? v : fast_sigmoid(v);

            if (stage < 2) {
                const int st = stage + 1;
                #pragma unroll
                for (int t = 0; t < 3; ++t) {
                    if (t < kcnt) {
                        int k = kbeg + t;
                        s_phi[rr][uu * NBAS + k] =
                            fast_tanh((h - s_c[st][k]) * s_iw[st][k]);
                    }
                }
            } else {
                if (part == 0) s_val[rr][uu] = h;
            }
        }
        __syncthreads();
    }

    // ---- head: logits[r][c] = h . W[:,c] + b[c] ----
    if (tid < RPB * NCLS) {
        int r = tid / NCLS, c = tid % NCLS;
        float s = s_b[c];
        #pragma unroll
        for (int o = 0; o < HIDN; ++o)
            s = fmaf(s_val[r][o], s_W[o * NCLS + c], s);
        out[(r0 + r) * NCLS + c] = s;
    }
}

extern "C" void kernel_launch(void* const* d_in, const int* in_sizes, int n_in,
                              void* d_out, int out_size) {
    (void)in_sizes; (void)n_in; (void)out_size;
    const float* x  = (const float*)d_in[0];
    const float* c0 = (const float*)d_in[1];
    const float* w0 = (const float*)d_in[2];
    const float* C0 = (const float*)d_in[3];
    const float* c1 = (const float*)d_in[4];
    const float* w1 = (const float*)d_in[5];
    const float* C1 = (const float*)d_in[6];
    const float* c2 = (const float*)d_in[7];
    const float* w2 = (const float*)d_in[8];
    const float* C2 = (const float*)d_in[9];
    const float* W  = (const float*)d_in[10];
    const float* b  = (const float*)d_in[11];
    float* out = (float*)d_out;

    node_rnn_fused_kernel<<<NBLK, NTHR>>>(x, c0, w0, C0, c1, w1, C1,
                                          c2, w2, C2, W, b, out);
}